// round 2
// baseline (speedup 1.0000x reference)
#include <cuda_runtime.h>
#include <cuda_bf16.h>

// Problem constants
#define Bz 4
#define Nz 128
#define Mz 128
#define Dz 256
#define BDz 1024

// Scratch in device globals (no allocation allowed)
__device__ float g_Aw[Dz * Dz];        // Aw[d][e] = sum_k A[d,e,k] * W[k]   (256 KB)
__device__ float g_T[Bz * Nz * Dz];    // T[b,n,e] = sum_d X[b,n,d] * Aw[d,e] (512 KB)

// ---------------------------------------------------------------------------
// Kernel 1: Aw[row] = dot(A[row*1024 : row*1024+1024], W), row = d*256 + e
// One warp per row. W cached in shared memory as float4.
// 65536 rows / 8 warps per block = 8192 blocks. HBM-bound (268 MB streamed).
// ---------------------------------------------------------------------------
__global__ __launch_bounds__(256) void k1_reduce_A(const float* __restrict__ A,
                                                   const float* __restrict__ W) {
    __shared__ float4 sW[BDz / 4];  // 1024 floats = 256 float4 = 4 KB
    int tid = threadIdx.x;
    sW[tid] = reinterpret_cast<const float4*>(W)[tid];
    __syncthreads();

    int warp = tid >> 5;
    int lane = tid & 31;
    long row = (long)blockIdx.x * 8 + warp;          // [0, 65536)
    const float4* Arow = reinterpret_cast<const float4*>(A) + row * (BDz / 4);

    float acc = 0.0f;
#pragma unroll
    for (int i = 0; i < 8; i++) {
        float4 a = Arow[i * 32 + lane];
        float4 w = sW[i * 32 + lane];
        acc += a.x * w.x + a.y * w.y + a.z * w.z + a.w * w.w;
    }
#pragma unroll
    for (int off = 16; off; off >>= 1)
        acc += __shfl_xor_sync(0xffffffffu, acc, off);
    if (lane == 0) g_Aw[row] = acc;
}

// ---------------------------------------------------------------------------
// Kernel 2: T[r,e] = sum_d Xall[r,d] * Aw[d,e]   (512x256 @ 256x256)
// 32x32 output tile per block, 256 threads (32 x-cols, 8 y-rows, 4 rows/thread)
// ---------------------------------------------------------------------------
__global__ __launch_bounds__(256) void k2_x_aw(const float* __restrict__ X) {
    __shared__ float sX[32][33];
    __shared__ float sA[32][33];

    int tx = threadIdx.x & 31;
    int ty = threadIdx.x >> 5;   // 0..7
    int tid = threadIdx.x;
    int r0 = blockIdx.y * 32;    // row tile (0..480)
    int e0 = blockIdx.x * 32;    // col tile (0..224)

    float acc[4] = {0.f, 0.f, 0.f, 0.f};

#pragma unroll 1
    for (int kt = 0; kt < Dz / 32; kt++) {
        int k0 = kt * 32;
#pragma unroll
        for (int t = 0; t < 4; t++) {
            int idx = tid + t * 256;
            int i = idx >> 5, j = idx & 31;
            sX[i][j] = X[(long)(r0 + i) * Dz + k0 + j];
            sA[i][j] = g_Aw[(long)(k0 + i) * Dz + e0 + j];
        }
        __syncthreads();
#pragma unroll
        for (int k = 0; k < 32; k++) {
            float a = sA[k][tx];
#pragma unroll
            for (int rr = 0; rr < 4; rr++)
                acc[rr] += sX[ty + 8 * rr][k] * a;
        }
        __syncthreads();
    }
#pragma unroll
    for (int rr = 0; rr < 4; rr++)
        g_T[(long)(r0 + ty + 8 * rr) * Dz + e0 + tx] = acc[rr];
}

// ---------------------------------------------------------------------------
// Kernel 3: S[b,n,m] = sum_e T[b,n,e] * Y[b,m,e] + bias
// Per batch: (128x256) @ (128x256)^T. 32x32 tile per block.
// Grid: (4 m-tiles, 4 n-tiles, 4 batches) = 64 blocks.
// ---------------------------------------------------------------------------
__global__ __launch_bounds__(256) void k3_t_yt(const float* __restrict__ Y,
                                               const float* __restrict__ bias,
                                               float* __restrict__ S) {
    __shared__ float sT[32][33];
    __shared__ float sY[32][33];

    int tx = threadIdx.x & 31;
    int ty = threadIdx.x >> 5;
    int tid = threadIdx.x;
    int b  = blockIdx.z;
    int n0 = blockIdx.y * 32;
    int m0 = blockIdx.x * 32;

    const float* Tb = g_T + (long)b * Nz * Dz;
    const float* Yb = Y   + (long)b * Mz * Dz;

    float acc[4] = {0.f, 0.f, 0.f, 0.f};

#pragma unroll 1
    for (int kt = 0; kt < Dz / 32; kt++) {
        int k0 = kt * 32;
#pragma unroll
        for (int t = 0; t < 4; t++) {
            int idx = tid + t * 256;
            int i = idx >> 5, j = idx & 31;
            sT[i][j] = Tb[(long)(n0 + i) * Dz + k0 + j];
            sY[i][j] = Yb[(long)(m0 + i) * Dz + k0 + j];
        }
        __syncthreads();
#pragma unroll
        for (int k = 0; k < 32; k++) {
            float yv = sY[tx][k];
#pragma unroll
            for (int rr = 0; rr < 4; rr++)
                acc[rr] += sT[ty + 8 * rr][k] * yv;
        }
        __syncthreads();
    }

    float bv = bias[0];
#pragma unroll
    for (int rr = 0; rr < 4; rr++)
        S[(long)b * Nz * Mz + (long)(n0 + ty + 8 * rr) * Mz + m0 + tx] = acc[rr] + bv;
}

// ---------------------------------------------------------------------------
// Launch: inputs in order X, Y, A, W, b  (per setup_inputs)
// ---------------------------------------------------------------------------
extern "C" void kernel_launch(void* const* d_in, const int* in_sizes, int n_in,
                              void* d_out, int out_size) {
    const float* X = (const float*)d_in[0];  // [4,128,256]
    const float* Y = (const float*)d_in[1];  // [4,128,256]
    const float* A = (const float*)d_in[2];  // [256,256,1024]
    const float* W = (const float*)d_in[3];  // [1,1024]
    const float* b = (const float*)d_in[4];  // [1]
    float* S = (float*)d_out;                // [4,128,128]

    // Kernel 1: 65536 rows, 8 warps/block
    k1_reduce_A<<<8192, 256>>>(A, W);

    // Kernel 2: T (512 x 256) in 32x32 tiles -> grid (8, 16)
    {
        dim3 grid(Dz / 32, (Bz * Nz) / 32);
        k2_x_aw<<<grid, 256>>>(X);
    }

    // Kernel 3: S (4 x 128 x 128) in 32x32 tiles -> grid (4, 4, 4)
    {
        dim3 grid(Mz / 32, Nz / 32, Bz);
        k3_t_yt<<<grid, 256>>>(Y, b, S);
    }
}

// round 4
// speedup vs baseline: 1.4505x; 1.4505x over previous
#include <cuda_runtime.h>
#include <cuda_bf16.h>

// Problem constants
#define Bz 4
#define Nz 128
#define Mz 128
#define Dz 256
#define BDz 1024

#define KSPLIT 4
#define TSZ (Bz * Nz * Dz)      // 131072 elems (T)
#define SSZ (Bz * Nz * Mz)      // 65536 elems (S)

// Scratch in device globals (no allocation allowed). Fully overwritten each
// launch -> deterministic, no zeroing needed.
__device__ float g_Aw[Dz * Dz];                // Aw[d][e] = sum_k A[d,e,k]*W[k]
__device__ float g_Tp[KSPLIT * TSZ];           // T partials, split over d
__device__ float g_Sp[KSPLIT * SSZ];           // S partials, split over e

// ---------------------------------------------------------------------------
// Kernel 1: Aw[row] = dot(A[row*1024 .. +1024], W), row = d*256 + e
// One warp per row; W in smem; float4 streaming loads (A is read once).
// HBM-bound: 268 MB streamed.
// ---------------------------------------------------------------------------
__global__ __launch_bounds__(256) void k1_reduce_A(const float* __restrict__ A,
                                                   const float* __restrict__ W) {
    __shared__ float4 sW[BDz / 4];
    int tid = threadIdx.x;
    sW[tid] = reinterpret_cast<const float4*>(W)[tid];
    __syncthreads();

    int warp = tid >> 5;
    int lane = tid & 31;
    long row = (long)blockIdx.x * 8 + warp;
    const float4* Arow = reinterpret_cast<const float4*>(A) + row * (BDz / 4);

    float acc = 0.0f;
#pragma unroll
    for (int i = 0; i < 8; i++) {
        float4 a = __ldcs(&Arow[i * 32 + lane]);   // evict-first: A is one-shot
        float4 w = sW[i * 32 + lane];
        acc += a.x * w.x + a.y * w.y + a.z * w.z + a.w * w.w;
    }
#pragma unroll
    for (int off = 16; off; off >>= 1)
        acc += __shfl_xor_sync(0xffffffffu, acc, off);
    if (lane == 0) g_Aw[row] = acc;
}

// ---------------------------------------------------------------------------
// Kernel 2 (split-K): Tp[ks][r,e] = sum_{d in chunk ks} X[r,d] * Aw[d,e]
// 64x64 tile, 256 threads, 4x4 register blocking, K-chunk = 64.
// Grid: (e-tiles=4, r-tiles=8, ks=4) = 128 blocks.
// ---------------------------------------------------------------------------
__global__ __launch_bounds__(256) void k2_split(const float* __restrict__ X) {
    __shared__ float sX[64][65];   // [r][k]
    __shared__ float sA[64][65];   // [k][e]

    int tid = threadIdx.x;
    int tx = tid & 15;            // e group
    int ty = tid >> 4;            // r group
    int e0 = blockIdx.x * 64;
    int r0 = blockIdx.y * 64;
    int ks = blockIdx.z;
    int kc = ks * 64;

#pragma unroll
    for (int t = 0; t < 4; t++) {
        int lin = tid + t * 256;           // 0..1023
        int row = lin >> 4;                // 0..63
        int c4  = (lin & 15) << 2;         // 0,4,..,60
        float4 xv = *reinterpret_cast<const float4*>(&X[(r0 + row) * Dz + kc + c4]);
        sX[row][c4 + 0] = xv.x; sX[row][c4 + 1] = xv.y;
        sX[row][c4 + 2] = xv.z; sX[row][c4 + 3] = xv.w;
        float4 av = *reinterpret_cast<const float4*>(&g_Aw[(kc + row) * Dz + e0 + c4]);
        sA[row][c4 + 0] = av.x; sA[row][c4 + 1] = av.y;
        sA[row][c4 + 2] = av.z; sA[row][c4 + 3] = av.w;
    }
    __syncthreads();

    float acc[4][4] = {};
#pragma unroll 16
    for (int k = 0; k < 64; k++) {
        float xv[4], av[4];
#pragma unroll
        for (int i = 0; i < 4; i++) xv[i] = sX[ty + 16 * i][k];
#pragma unroll
        for (int j = 0; j < 4; j++) av[j] = sA[k][tx + 16 * j];
#pragma unroll
        for (int i = 0; i < 4; i++)
#pragma unroll
            for (int j = 0; j < 4; j++)
                acc[i][j] += xv[i] * av[j];
    }

    float* out = g_Tp + (long)ks * TSZ;
#pragma unroll
    for (int i = 0; i < 4; i++)
#pragma unroll
        for (int j = 0; j < 4; j++)
            out[(r0 + ty + 16 * i) * Dz + e0 + tx + 16 * j] = acc[i][j];
}

// ---------------------------------------------------------------------------
// Kernel 3 (split-K over e): Sp[ks][b,n,m] = sum_{e in chunk} T[b,n,e]*Y[b,m,e]
// T is reconstructed from the 4 d-partials during the smem load (L2-hot).
// Grid: (m-tiles=2, n-tiles=2, b*4+ks = 16) = 64 blocks.
// ---------------------------------------------------------------------------
__global__ __launch_bounds__(256) void k3_split(const float* __restrict__ Y) {
    __shared__ float sT[64][65];   // [n][e]
    __shared__ float sY[64][65];   // [m][e]

    int tid = threadIdx.x;
    int tx = tid & 15;            // m group
    int ty = tid >> 4;            // n group
    int m0 = blockIdx.x * 64;
    int n0 = blockIdx.y * 64;
    int b  = blockIdx.z >> 2;
    int ks = blockIdx.z & 3;
    int kc = ks * 64;             // e chunk

    long tb = (long)b * Nz * Dz;
    const float* Yb = Y + (long)b * Mz * Dz;

#pragma unroll
    for (int t = 0; t < 4; t++) {
        int lin = tid + t * 256;
        int row = lin >> 4;
        int c4  = (lin & 15) << 2;
        // Sum the 4 d-partials of T while loading
        long base = tb + (long)(n0 + row) * Dz + kc + c4;
        float4 t0 = *reinterpret_cast<const float4*>(&g_Tp[0 * TSZ + base]);
        float4 t1 = *reinterpret_cast<const float4*>(&g_Tp[1 * TSZ + base]);
        float4 t2 = *reinterpret_cast<const float4*>(&g_Tp[2 * TSZ + base]);
        float4 t3 = *reinterpret_cast<const float4*>(&g_Tp[3 * TSZ + base]);
        sT[row][c4 + 0] = t0.x + t1.x + t2.x + t3.x;
        sT[row][c4 + 1] = t0.y + t1.y + t2.y + t3.y;
        sT[row][c4 + 2] = t0.z + t1.z + t2.z + t3.z;
        sT[row][c4 + 3] = t0.w + t1.w + t2.w + t3.w;
        float4 yv = *reinterpret_cast<const float4*>(&Yb[(long)(m0 + row) * Dz + kc + c4]);
        sY[row][c4 + 0] = yv.x; sY[row][c4 + 1] = yv.y;
        sY[row][c4 + 2] = yv.z; sY[row][c4 + 3] = yv.w;
    }
    __syncthreads();

    float acc[4][4] = {};
#pragma unroll 16
    for (int e = 0; e < 64; e++) {
        float tv[4], yv[4];
#pragma unroll
        for (int i = 0; i < 4; i++) tv[i] = sT[ty + 16 * i][e];
#pragma unroll
        for (int j = 0; j < 4; j++) yv[j] = sY[tx + 16 * j][e];
#pragma unroll
        for (int i = 0; i < 4; i++)
#pragma unroll
            for (int j = 0; j < 4; j++)
                acc[i][j] += tv[i] * yv[j];
    }

    float* out = g_Sp + (long)ks * SSZ + (long)b * Nz * Mz;
#pragma unroll
    for (int i = 0; i < 4; i++)
#pragma unroll
        for (int j = 0; j < 4; j++)
            out[(n0 + ty + 16 * i) * Mz + m0 + tx + 16 * j] = acc[i][j];
}

// ---------------------------------------------------------------------------
// Kernel 4: S = sum_ks Sp[ks] + bias   (65536 elems, float4)
// ---------------------------------------------------------------------------
__global__ __launch_bounds__(256) void k4_final(const float* __restrict__ bias,
                                                float* __restrict__ S) {
    int idx = blockIdx.x * 256 + threadIdx.x;      // 16384 float4s
    float bv = bias[0];
    const float4* p0 = reinterpret_cast<const float4*>(g_Sp + 0 * SSZ);
    const float4* p1 = reinterpret_cast<const float4*>(g_Sp + 1 * SSZ);
    const float4* p2 = reinterpret_cast<const float4*>(g_Sp + 2 * SSZ);
    const float4* p3 = reinterpret_cast<const float4*>(g_Sp + 3 * SSZ);
    float4 a = p0[idx], b2 = p1[idx], c = p2[idx], d = p3[idx];
    float4 r;
    r.x = a.x + b2.x + c.x + d.x + bv;
    r.y = a.y + b2.y + c.y + d.y + bv;
    r.z = a.z + b2.z + c.z + d.z + bv;
    r.w = a.w + b2.w + c.w + d.w + bv;
    reinterpret_cast<float4*>(S)[idx] = r;
}

// ---------------------------------------------------------------------------
// Launch: inputs in order X, Y, A, W, b
// ---------------------------------------------------------------------------
extern "C" void kernel_launch(void* const* d_in, const int* in_sizes, int n_in,
                              void* d_out, int out_size) {
    const float* X = (const float*)d_in[0];  // [4,128,256]
    const float* Y = (const float*)d_in[1];  // [4,128,256]
    const float* A = (const float*)d_in[2];  // [256,256,1024]
    const float* W = (const float*)d_in[3];  // [1,1024]
    const float* b = (const float*)d_in[4];  // [1]
    float* S = (float*)d_out;                // [4,128,128]

    k1_reduce_A<<<8192, 256>>>(A, W);

    {
        dim3 grid(Dz / 64, (Bz * Nz) / 64, KSPLIT);   // (4, 8, 4) = 128 blocks
        k2_split<<<grid, 256>>>(X);
    }
    {
        dim3 grid(Mz / 64, Nz / 64, Bz * KSPLIT);     // (2, 2, 16) = 64 blocks
        k3_split<<<grid, 256>>>(Y);
    }
    k4_final<<<SSZ / 4 / 256, 256>>>(b, S);           // 64 blocks
}